// round 8
// baseline (speedup 1.0000x reference)
#include <cuda_runtime.h>
#include <cuda_bf16.h>
#include <cstdint>

#define NROWS 16384
#define DDIM  512
#define TM    128            // CTA tile rows   (first)
#define TN    256            // CTA tile cols   (second)
#define KC    64             // K-chunk
#define NCHUNK (DDIM / KC)   // 8
#define NTHREADS 512         // 16 warps: 4 (M) x 4 (N)

#define SROW   72                       // smem row stride in bf16 (144B, conflict-free)
#define SROWB  (SROW * 2)               // 144 bytes
#define A_SMEM_B (TM * SROWB)           // 18432
#define B_SMEM_B (TN * SROWB)           // 36864
#define BUF_B  (A_SMEM_B + B_SMEM_B)    // 55296
#define DSMEM_BYTES (2 * BUF_B)         // 110592

// bf16 copies of the inputs, plain row-major (allocation-free scratch)
__device__ __nv_bfloat16 g_fb[NROWS * DDIM];
__device__ __nv_bfloat16 g_sb[NROWS * DDIM];

// ---------------------------------------------------------------------------
// PTX helpers (all plain sm_80/sm_90 PTX — nothing gated on sm_103a)
// ---------------------------------------------------------------------------
__device__ __forceinline__ uint32_t smem_u32(const void* p) {
    uint32_t a;
    asm("{ .reg .u64 t; cvta.to.shared.u64 t, %1; cvt.u32.u64 %0, t; }"
        : "=r"(a) : "l"(p));
    return a;
}

__device__ __forceinline__ void cp_async16(uint32_t dst, const void* src) {
    asm volatile("cp.async.cg.shared.global [%0], [%1], 16;"
                 :: "r"(dst), "l"(src));
}
#define CP_COMMIT() asm volatile("cp.async.commit_group;" ::: "memory")
#define CP_WAIT(n)  asm volatile("cp.async.wait_group %0;" :: "n"(n) : "memory")

__device__ __forceinline__ void ldsm_x4(uint32_t& r0, uint32_t& r1,
                                        uint32_t& r2, uint32_t& r3, uint32_t a) {
    asm volatile("ldmatrix.sync.aligned.m8n8.x4.shared.b16 {%0,%1,%2,%3}, [%4];"
                 : "=r"(r0), "=r"(r1), "=r"(r2), "=r"(r3) : "r"(a));
}

__device__ __forceinline__ void mma16816(float* d, const uint32_t* a,
                                         const uint32_t* b) {
    asm volatile(
        "mma.sync.aligned.m16n8k16.row.col.f32.bf16.bf16.f32 "
        "{%0,%1,%2,%3}, {%4,%5,%6,%7}, {%8,%9}, {%0,%1,%2,%3};"
        : "+f"(d[0]), "+f"(d[1]), "+f"(d[2]), "+f"(d[3])
        : "r"(a[0]), "r"(a[1]), "r"(a[2]), "r"(a[3]), "r"(b[0]), "r"(b[1]));
}

// ---------------------------------------------------------------------------
// Kernel 1: fp32 -> bf16 (row-major) + zero the output accumulator
// ---------------------------------------------------------------------------
__global__ void prep_kernel(const float* __restrict__ f,
                            const float* __restrict__ s,
                            float* __restrict__ out) {
    const int i = blockIdx.x * blockDim.x + threadIdx.x;
    if (i == 0) out[0] = 0.0f;
    const int nquads = NROWS * DDIM / 8;          // 1,048,576 (8 bf16 per quad)
    const int stride = gridDim.x * blockDim.x;
    const float4* f4 = (const float4*)f;
    const float4* s4 = (const float4*)s;
    uint4* fd = (uint4*)g_fb;
    uint4* sd = (uint4*)g_sb;
    for (int q = i; q < nquads; q += stride) {
        const int src4 = q * 2;
        {
            float4 a0 = f4[src4], a1 = f4[src4 + 1];
            uint4 v;
            ((__nv_bfloat162*)&v)[0] = __floats2bfloat162_rn(a0.x, a0.y);
            ((__nv_bfloat162*)&v)[1] = __floats2bfloat162_rn(a0.z, a0.w);
            ((__nv_bfloat162*)&v)[2] = __floats2bfloat162_rn(a1.x, a1.y);
            ((__nv_bfloat162*)&v)[3] = __floats2bfloat162_rn(a1.z, a1.w);
            fd[q] = v;
        }
        {
            float4 b0 = s4[src4], b1 = s4[src4 + 1];
            uint4 v;
            ((__nv_bfloat162*)&v)[0] = __floats2bfloat162_rn(b0.x, b0.y);
            ((__nv_bfloat162*)&v)[1] = __floats2bfloat162_rn(b0.z, b0.w);
            ((__nv_bfloat162*)&v)[2] = __floats2bfloat162_rn(b1.x, b1.y);
            ((__nv_bfloat162*)&v)[3] = __floats2bfloat162_rn(b1.z, b1.w);
            sd[q] = v;
        }
    }
}

// ---------------------------------------------------------------------------
// Kernel 2: 128x256 logits tile per CTA via bf16 mma.sync (HMMA), cp.async
// double-buffered mainloop, fused logsigmoid-loss epilogue from registers.
// ---------------------------------------------------------------------------
extern __shared__ __align__(16) char dyn_smem[];

__global__ void __launch_bounds__(NTHREADS, 1)
sigloss_kernel(const int* __restrict__ first_label,
               const int* __restrict__ second_label,
               const float* __restrict__ scale_p,
               const float* __restrict__ bias_p,
               float* __restrict__ out) {
    __shared__ int s_fl[TM];
    __shared__ int s_sl[TN];
    __shared__ float s_part[16];

    const int tid = threadIdx.x;
    const int wid = tid >> 5;
    const int lid = tid & 31;
    const int warpM = wid & 3;        // 4 M groups of 32 rows
    const int warpN = wid >> 2;       // 4 N groups of 64 cols
    const int tileN = blockIdx.x;     // 0..63
    const int tileM = blockIdx.y;     // 0..127

    if (tid < TN) s_sl[tid] = second_label[tileN * TN + tid];
    else if (tid < TN + TM) s_fl[tid - TN] = first_label[tileM * TM + (tid - TN)];
    const float scale = *scale_p;
    const float bias  = *bias_p;

    const char* Ab = (const char*)(g_fb + (size_t)tileM * TM * DDIM);
    const char* Bb = (const char*)(g_sb + (size_t)tileN * TN * DDIM);
    const uint32_t smem_base = smem_u32(dyn_smem);

    // issue cp.async for one K-chunk into buffer `buf`
    auto issue = [&](int c, int buf) {
        const uint32_t abase = smem_base + buf * BUF_B;
        const uint32_t bbase = abase + A_SMEM_B;
        const int coff = c * (KC * 2);            // 128 bytes into each row
        #pragma unroll
        for (int u = tid; u < (TM + TN) * 8; u += NTHREADS) {
            const int row = u >> 3;
            const int s8  = (u & 7) * 16;
            if (row < TM)
                cp_async16(abase + row * SROWB + s8,
                           Ab + (size_t)row * (DDIM * 2) + coff + s8);
            else {
                const int br = row - TM;
                cp_async16(bbase + br * SROWB + s8,
                           Bb + (size_t)br * (DDIM * 2) + coff + s8);
            }
        }
        CP_COMMIT();
    };

    float acc[2][8][4] = {};          // 64 fp32 accumulators / thread

    issue(0, 0);
    issue(1, 1);

    for (int c = 0; c < NCHUNK; ++c) {
        if (c == NCHUNK - 1) CP_WAIT(0); else CP_WAIT(1);
        __syncthreads();

        const uint32_t abase = smem_base + (c & 1) * BUF_B + (warpM * 32) * SROWB;
        const uint32_t bbase = smem_base + (c & 1) * BUF_B + A_SMEM_B
                             + (warpN * 64) * SROWB;
        #pragma unroll
        for (int ks = 0; ks < KC / 16; ++ks) {
            uint32_t a[2][4];
            #pragma unroll
            for (int mi = 0; mi < 2; ++mi) {
                // lanes 0-7: m0-7 kLo | 8-15: m8-15 kLo | 16-23: m0-7 kHi | 24-31: m8-15 kHi
                const uint32_t addr = abase + (mi * 16 + (lid & 15)) * SROWB
                                    + ks * 32 + ((lid >> 4) & 1) * 16;
                ldsm_x4(a[mi][0], a[mi][1], a[mi][2], a[mi][3], addr);
            }
            uint32_t b[4][4];
            #pragma unroll
            for (int nq = 0; nq < 4; ++nq) {
                // lanes 0-7: n0-7 kLo | 8-15: n0-7 kHi | 16-23: n8-15 kLo | 24-31: n8-15 kHi
                const uint32_t nrow = nq * 16 + (lid & 7) + ((lid >> 4) & 1) * 8;
                const uint32_t addr = bbase + nrow * SROWB
                                    + ks * 32 + ((lid >> 3) & 1) * 16;
                ldsm_x4(b[nq][0], b[nq][1], b[nq][2], b[nq][3], addr);
            }
            #pragma unroll
            for (int mi = 0; mi < 2; ++mi)
                #pragma unroll
                for (int n8 = 0; n8 < 8; ++n8)
                    mma16816(acc[mi][n8], a[mi], &b[n8 >> 1][(n8 & 1) * 2]);
        }
        __syncthreads();
        if (c + 2 < NCHUNK) issue(c + 2, c & 1);
    }

    // ---- epilogue: logsigmoid loss from register accumulators ----
    // sum softplus(y) = sum max(y,0) + log( prod (1 + e^{-|y|}) ),
    // factors in (1,2] -> batch 16 per __logf (max prod 2^16, no overflow).
    const int gr = lid >> 2;          // fragment row 0..7
    const int gc = (lid & 3) * 2;     // fragment col (pair)
    float lsum = 0.0f;
    #pragma unroll
    for (int mi = 0; mi < 2; ++mi) {
        float prod = 1.0f;
        #pragma unroll
        for (int n8 = 0; n8 < 8; ++n8) {
            const int r0 = warpM * 32 + mi * 16 + gr;
            const int c0 = warpN * 64 + n8 * 8 + gc;
            const int fl0 = s_fl[r0], fl1 = s_fl[r0 + 8];
            const int sl0 = s_sl[c0], sl1 = s_sl[c0 + 1];
            const float* d = acc[mi][n8];
            #pragma unroll
            for (int e = 0; e < 4; ++e) {
                const int fl = (e < 2) ? fl0 : fl1;
                const int sl = (e & 1) ? sl1 : sl0;
                const float logit = fmaf(scale, d[e], bias);
                const float y = (fl == sl) ? -logit : logit;   // y = -label*logit
                lsum += fmaxf(y, 0.0f);
                prod *= 1.0f + __expf(-fabsf(y));
            }
            if ((n8 & 3) == 3) {       // flush every 16 factors
                lsum += __logf(prod);
                prod = 1.0f;
            }
        }
    }

    #pragma unroll
    for (int off = 16; off > 0; off >>= 1)
        lsum += __shfl_xor_sync(0xFFFFFFFFu, lsum, off);
    if (lid == 0) s_part[wid] = lsum;
    __syncthreads();

    if (tid == 0) {
        float tot = 0.0f;
        #pragma unroll
        for (int w = 0; w < 16; ++w) tot += s_part[w];
        atomicAdd(out, tot * (1.0f / (float)NROWS));
    }
}

// ---------------------------------------------------------------------------
// Launch
// ---------------------------------------------------------------------------
extern "C" void kernel_launch(void* const* d_in, const int* in_sizes, int n_in,
                              void* d_out, int out_size) {
    const float* f  = (const float*)d_in[0];   // first_features  [16384,512]
    const float* s  = (const float*)d_in[1];   // second_features [16384,512]
    const int*   fl = (const int*)d_in[2];     // first_label  [16384]
    const int*   sl = (const int*)d_in[3];     // second_label [16384]
    const float* sc = (const float*)d_in[4];   // logit_scale (scalar)
    const float* bs = (const float*)d_in[5];   // logit_bias  (scalar)
    float* out = (float*)d_out;

    cudaFuncSetAttribute(sigloss_kernel,
                         cudaFuncAttributeMaxDynamicSharedMemorySize,
                         DSMEM_BYTES);

    prep_kernel<<<2048, 256>>>(f, s, out);

    dim3 grid(NROWS / TN, NROWS / TM);         // 64 x 128
    sigloss_kernel<<<grid, NTHREADS, DSMEM_BYTES>>>(fl, sl, sc, bs, out);
}

// round 11
// speedup vs baseline: 1.1051x; 1.1051x over previous
#include <cuda_runtime.h>
#include <cuda_bf16.h>
#include <cstdint>

#define NROWS 16384
#define DDIM  512
#define TM    128            // CTA tile rows   (first)
#define TN    128            // CTA tile cols   (second)
#define KC    64             // K-chunk
#define NCHUNK (DDIM / KC)   // 8
#define NTHREADS 256         // 8 warps: 4 (M) x 2 (N); 2 CTAs/SM

#define SROW   72                       // smem row stride in bf16 (144B, conflict-free)
#define SROWB  (SROW * 2)               // 144 bytes
#define A_SMEM_B (TM * SROWB)           // 18432
#define B_SMEM_B (TN * SROWB)           // 18432
#define BUF_B  (A_SMEM_B + B_SMEM_B)    // 36864
#define DSMEM_BYTES (2 * BUF_B)         // 73728 -> 2 CTAs/SM (147KB < 228KB)

// bf16 copies of the inputs, plain row-major (allocation-free scratch)
__device__ __nv_bfloat16 g_fb[NROWS * DDIM];
__device__ __nv_bfloat16 g_sb[NROWS * DDIM];

// ---------------------------------------------------------------------------
// PTX helpers (all plain sm_80/sm_90 PTX — nothing gated on sm_103a)
// ---------------------------------------------------------------------------
__device__ __forceinline__ uint32_t smem_u32(const void* p) {
    uint32_t a;
    asm("{ .reg .u64 t; cvta.to.shared.u64 t, %1; cvt.u32.u64 %0, t; }"
        : "=r"(a) : "l"(p));
    return a;
}

__device__ __forceinline__ void cp_async16(uint32_t dst, const void* src) {
    asm volatile("cp.async.cg.shared.global [%0], [%1], 16;"
                 :: "r"(dst), "l"(src));
}
#define CP_COMMIT() asm volatile("cp.async.commit_group;" ::: "memory")
#define CP_WAIT(n)  asm volatile("cp.async.wait_group %0;" :: "n"(n) : "memory")

__device__ __forceinline__ void ldsm_x4(uint32_t& r0, uint32_t& r1,
                                        uint32_t& r2, uint32_t& r3, uint32_t a) {
    asm volatile("ldmatrix.sync.aligned.m8n8.x4.shared.b16 {%0,%1,%2,%3}, [%4];"
                 : "=r"(r0), "=r"(r1), "=r"(r2), "=r"(r3) : "r"(a));
}

__device__ __forceinline__ void mma16816(float* d, const uint32_t* a,
                                         const uint32_t* b) {
    asm volatile(
        "mma.sync.aligned.m16n8k16.row.col.f32.bf16.bf16.f32 "
        "{%0,%1,%2,%3}, {%4,%5,%6,%7}, {%8,%9}, {%0,%1,%2,%3};"
        : "+f"(d[0]), "+f"(d[1]), "+f"(d[2]), "+f"(d[3])
        : "r"(a[0]), "r"(a[1]), "r"(a[2]), "r"(a[3]), "r"(b[0]), "r"(b[1]));
}

// ---------------------------------------------------------------------------
// Kernel 1: fp32 -> bf16 (row-major) + zero the output accumulator
// ---------------------------------------------------------------------------
__global__ void prep_kernel(const float* __restrict__ f,
                            const float* __restrict__ s,
                            float* __restrict__ out) {
    const int i = blockIdx.x * blockDim.x + threadIdx.x;
    if (i == 0) out[0] = 0.0f;
    const int nquads = NROWS * DDIM / 8;          // 1,048,576 (8 bf16 per quad)
    const int stride = gridDim.x * blockDim.x;
    const float4* f4 = (const float4*)f;
    const float4* s4 = (const float4*)s;
    uint4* fd = (uint4*)g_fb;
    uint4* sd = (uint4*)g_sb;
    for (int q = i; q < nquads; q += stride) {
        const int src4 = q * 2;
        {
            float4 a0 = f4[src4], a1 = f4[src4 + 1];
            uint4 v;
            ((__nv_bfloat162*)&v)[0] = __floats2bfloat162_rn(a0.x, a0.y);
            ((__nv_bfloat162*)&v)[1] = __floats2bfloat162_rn(a0.z, a0.w);
            ((__nv_bfloat162*)&v)[2] = __floats2bfloat162_rn(a1.x, a1.y);
            ((__nv_bfloat162*)&v)[3] = __floats2bfloat162_rn(a1.z, a1.w);
            fd[q] = v;
        }
        {
            float4 b0 = s4[src4], b1 = s4[src4 + 1];
            uint4 v;
            ((__nv_bfloat162*)&v)[0] = __floats2bfloat162_rn(b0.x, b0.y);
            ((__nv_bfloat162*)&v)[1] = __floats2bfloat162_rn(b0.z, b0.w);
            ((__nv_bfloat162*)&v)[2] = __floats2bfloat162_rn(b1.x, b1.y);
            ((__nv_bfloat162*)&v)[3] = __floats2bfloat162_rn(b1.z, b1.w);
            sd[q] = v;
        }
    }
}

// ---------------------------------------------------------------------------
// Kernel 2: 128x128 logits tile per CTA via bf16 mma.sync (HMMA), cp.async
// double-buffered mainloop, 2 CTAs/SM for cross-CTA latency hiding,
// fused logsigmoid-loss epilogue from registers.
// ---------------------------------------------------------------------------
extern __shared__ __align__(16) char dyn_smem[];

__global__ void __launch_bounds__(NTHREADS, 2)
sigloss_kernel(const int* __restrict__ first_label,
               const int* __restrict__ second_label,
               const float* __restrict__ scale_p,
               const float* __restrict__ bias_p,
               float* __restrict__ out) {
    __shared__ int s_fl[TM];
    __shared__ int s_sl[TN];
    __shared__ float s_part[8];

    const int tid = threadIdx.x;
    const int wid = tid >> 5;
    const int lid = tid & 31;
    const int warpM = wid & 3;        // 4 M groups of 32 rows
    const int warpN = wid >> 2;       // 2 N groups of 64 cols
    const int tileN = blockIdx.x;     // 0..127
    const int tileM = blockIdx.y;     // 0..127

    if (tid < TN) s_sl[tid] = second_label[tileN * TN + tid];
    else s_fl[tid - TN] = first_label[tileM * TM + (tid - TN)];
    const float scale = *scale_p;
    const float bias  = *bias_p;

    const char* Ab = (const char*)(g_fb + (size_t)tileM * TM * DDIM);
    const char* Bb = (const char*)(g_sb + (size_t)tileN * TN * DDIM);
    const uint32_t smem_base = smem_u32(dyn_smem);

    // issue cp.async for one K-chunk into buffer `buf`
    auto issue = [&](int c, int buf) {
        const uint32_t abase = smem_base + buf * BUF_B;
        const uint32_t bbase = abase + A_SMEM_B;
        const int coff = c * (KC * 2);            // 128 bytes into each row
        #pragma unroll
        for (int u = tid; u < (TM + TN) * 8; u += NTHREADS) {
            const int row = u >> 3;
            const int s8  = (u & 7) * 16;
            if (row < TM)
                cp_async16(abase + row * SROWB + s8,
                           Ab + (size_t)row * (DDIM * 2) + coff + s8);
            else {
                const int br = row - TM;
                cp_async16(bbase + br * SROWB + s8,
                           Bb + (size_t)br * (DDIM * 2) + coff + s8);
            }
        }
        CP_COMMIT();
    };

    float acc[2][8][4] = {};          // 64 fp32 accumulators / thread

    issue(0, 0);
    issue(1, 1);

    for (int c = 0; c < NCHUNK; ++c) {
        if (c == NCHUNK - 1) CP_WAIT(0); else CP_WAIT(1);
        __syncthreads();

        const uint32_t abase = smem_base + (c & 1) * BUF_B + (warpM * 32) * SROWB;
        const uint32_t bbase = smem_base + (c & 1) * BUF_B + A_SMEM_B
                             + (warpN * 64) * SROWB;
        #pragma unroll
        for (int ks = 0; ks < KC / 16; ++ks) {
            uint32_t a[2][4];
            #pragma unroll
            for (int mi = 0; mi < 2; ++mi) {
                // lanes 0-7: m0-7 kLo | 8-15: m8-15 kLo | 16-23: m0-7 kHi | 24-31: m8-15 kHi
                const uint32_t addr = abase + (mi * 16 + (lid & 15)) * SROWB
                                    + ks * 32 + ((lid >> 4) & 1) * 16;
                ldsm_x4(a[mi][0], a[mi][1], a[mi][2], a[mi][3], addr);
            }
            uint32_t b[4][4];
            #pragma unroll
            for (int nq = 0; nq < 4; ++nq) {
                // lanes 0-7: n0-7 kLo | 8-15: n0-7 kHi | 16-23: n8-15 kLo | 24-31: n8-15 kHi
                const uint32_t nrow = nq * 16 + (lid & 7) + ((lid >> 4) & 1) * 8;
                const uint32_t addr = bbase + nrow * SROWB
                                    + ks * 32 + ((lid >> 3) & 1) * 16;
                ldsm_x4(b[nq][0], b[nq][1], b[nq][2], b[nq][3], addr);
            }
            #pragma unroll
            for (int mi = 0; mi < 2; ++mi)
                #pragma unroll
                for (int n8 = 0; n8 < 8; ++n8)
                    mma16816(acc[mi][n8], a[mi], &b[n8 >> 1][(n8 & 1) * 2]);
        }
        __syncthreads();
        if (c + 2 < NCHUNK) issue(c + 2, c & 1);
    }

    // ---- epilogue: logsigmoid loss from register accumulators ----
    // sum softplus(y) = sum max(y,0) + log( prod (1 + e^{-|y|}) ),
    // factors in (1,2] -> batch 16 per __logf (max prod 2^16, no overflow).
    const int gr = lid >> 2;          // fragment row 0..7
    const int gc = (lid & 3) * 2;     // fragment col (pair)
    float lsum = 0.0f;
    #pragma unroll
    for (int mi = 0; mi < 2; ++mi) {
        float prod = 1.0f;
        #pragma unroll
        for (int n8 = 0; n8 < 8; ++n8) {
            const int r0 = warpM * 32 + mi * 16 + gr;
            const int c0 = warpN * 64 + n8 * 8 + gc;
            const int fl0 = s_fl[r0], fl1 = s_fl[r0 + 8];
            const int sl0 = s_sl[c0], sl1 = s_sl[c0 + 1];
            const float* d = acc[mi][n8];
            #pragma unroll
            for (int e = 0; e < 4; ++e) {
                const int fl = (e < 2) ? fl0 : fl1;
                const int sl = (e & 1) ? sl1 : sl0;
                const float logit = fmaf(scale, d[e], bias);
                const float y = (fl == sl) ? -logit : logit;   // y = -label*logit
                lsum += fmaxf(y, 0.0f);
                prod *= 1.0f + __expf(-fabsf(y));
            }
            if ((n8 & 3) == 3) {       // flush every 16 factors
                lsum += __logf(prod);
                prod = 1.0f;
            }
        }
    }

    #pragma unroll
    for (int off = 16; off > 0; off >>= 1)
        lsum += __shfl_xor_sync(0xFFFFFFFFu, lsum, off);
    if (lid == 0) s_part[wid] = lsum;
    __syncthreads();

    if (tid == 0) {
        float tot = 0.0f;
        #pragma unroll
        for (int w = 0; w < 8; ++w) tot += s_part[w];
        atomicAdd(out, tot * (1.0f / (float)NROWS));
    }
}

// ---------------------------------------------------------------------------
// Launch
// ---------------------------------------------------------------------------
extern "C" void kernel_launch(void* const* d_in, const int* in_sizes, int n_in,
                              void* d_out, int out_size) {
    const float* f  = (const float*)d_in[0];   // first_features  [16384,512]
    const float* s  = (const float*)d_in[1];   // second_features [16384,512]
    const int*   fl = (const int*)d_in[2];     // first_label  [16384]
    const int*   sl = (const int*)d_in[3];     // second_label [16384]
    const float* sc = (const float*)d_in[4];   // logit_scale (scalar)
    const float* bs = (const float*)d_in[5];   // logit_bias  (scalar)
    float* out = (float*)d_out;

    cudaFuncSetAttribute(sigloss_kernel,
                         cudaFuncAttributeMaxDynamicSharedMemorySize,
                         DSMEM_BYTES);

    prep_kernel<<<2048, 256>>>(f, s, out);

    dim3 grid(NROWS / TN, NROWS / TM);         // 128 x 128
    sigloss_kernel<<<grid, NTHREADS, DSMEM_BYTES>>>(fl, sl, sc, bs, out);
}